// round 1
// baseline (speedup 1.0000x reference)
#include <cuda_runtime.h>

#define BLOCK 128
#define DK 64

using ull = unsigned long long;

__device__ __forceinline__ ull fma2(ull a, ull b, ull c) {
    ull d;
    asm("fma.rn.f32x2 %0, %1, %2, %3;" : "=l"(d) : "l"(a), "l"(b), "l"(c));
    return d;
}
__device__ __forceinline__ ull add2(ull a, ull b) {
    ull d;
    asm("add.rn.f32x2 %0, %1, %2;" : "=l"(d) : "l"(a), "l"(b));
    return d;
}
__device__ __forceinline__ float2 unpack2(ull v) {
    float2 r;
    asm("mov.b64 {%0, %1}, %2;" : "=f"(r.x), "=f"(r.y) : "l"(v));
    return r;
}

// One thread per feature row. Block stages 128 rows through SMEM so every
// GMEM transaction (features in, logits out, probs out) is fully coalesced.
// XOR-swizzled float4 layout keeps per-thread private-row LDS conflict-free.
__global__ __launch_bounds__(BLOCK) void assign_kernel(
    const float4* __restrict__ feat4,
    const float4* __restrict__ proto4,
    float4* __restrict__ out4,
    int nrows)
{
    __shared__ float4 proto_s[DK * 16];    // 16 KB: 64 proto rows x 16 float4
    __shared__ float4 stage[BLOCK * 16];   // 32 KB: 128 rows x 16 float4 (reused in+out)

    const int tid = threadIdx.x;
    const long base = (long)blockIdx.x * BLOCK;
    const int rows = min(BLOCK, nrows - (int)base);
    const int cnt4 = rows * 16;

    // ---- stage prototypes (broadcast-read later, layout linear) ----
    #pragma unroll
    for (int i = 0; i < 8; i++)
        proto_s[tid + i * BLOCK] = proto4[tid + i * BLOCK];

    // ---- stage features, coalesced GMEM -> swizzled SMEM ----
    const float4* g = feat4 + base * 16;
    #pragma unroll
    for (int it = 0; it < 16; it++) {
        int idx = tid + it * BLOCK;
        float4 v = make_float4(0.f, 0.f, 0.f, 0.f);
        if (idx < cnt4) v = g[idx];
        int r = idx >> 4, c = idx & 15;
        stage[(r << 4) + (c ^ (r & 15))] = v;
    }
    __syncthreads();

    // ---- load own row into packed f32x2 registers ----
    ull f2[32];
    {
        const ulonglong2* sp = (const ulonglong2*)stage;
        #pragma unroll
        for (int i = 0; i < 16; i++) {
            ulonglong2 v = sp[(tid << 4) + (i ^ (tid & 15))];
            f2[2 * i]     = v.x;
            f2[2 * i + 1] = v.y;
        }
    }

    // ---- row norm: scale = 1 / (max(||f||, eps) * tau) ----
    ull n0 = 0, n1 = 0, n2 = 0, n3 = 0;
    #pragma unroll
    for (int i = 0; i < 8; i++) {
        n0 = fma2(f2[4 * i],     f2[4 * i],     n0);
        n1 = fma2(f2[4 * i + 1], f2[4 * i + 1], n1);
        n2 = fma2(f2[4 * i + 2], f2[4 * i + 2], n2);
        n3 = fma2(f2[4 * i + 3], f2[4 * i + 3], n3);
    }
    float2 ns = unpack2(add2(add2(n0, n1), add2(n2, n3)));
    float nrm = sqrtf(ns.x + ns.y);
    float scale = 1.0f / (fmaxf(nrm, 1e-8f) * 0.2f);

    // ---- logits: 64 dot products via packed FFMA2, proto from SMEM (broadcast) ----
    float* stf = (float*)stage;
    const ulonglong2* pp = (const ulonglong2*)proto_s;
    #pragma unroll 4
    for (int k = 0; k < DK; k++) {
        ull a0 = 0, a1 = 0, a2 = 0, a3 = 0;
        #pragma unroll
        for (int i = 0; i < 16; i += 2) {
            ulonglong2 p0 = pp[(k << 4) + i];
            ulonglong2 p1 = pp[(k << 4) + i + 1];
            a0 = fma2(f2[2 * i],     p0.x, a0);
            a1 = fma2(f2[2 * i + 1], p0.y, a1);
            a2 = fma2(f2[2 * i + 2], p1.x, a2);
            a3 = fma2(f2[2 * i + 3], p1.y, a3);
        }
        float2 s = unpack2(add2(add2(a0, a1), add2(a2, a3)));
        float lk = (s.x + s.y) * scale;
        // scalar store into own swizzled row region (no cross-thread hazard)
        stf[((tid << 4) + ((k >> 2) ^ (tid & 15))) * 4 + (k & 3)] = lk;
    }
    __syncthreads();

    // ---- coalesced store of logits ----
    float4* og = out4 + base * 16;
    #pragma unroll
    for (int it = 0; it < 16; it++) {
        int idx = tid + it * BLOCK;
        if (idx < cnt4) {
            int r = idx >> 4, c = idx & 15;
            og[idx] = stage[(r << 4) + (c ^ (r & 15))];
        }
    }
    __syncthreads();

    // ---- softmax: exp in place (|logit| <= 5, no max-shift needed), then scale ----
    float s0 = 0.f, s1 = 0.f;
    #pragma unroll 8
    for (int k = 0; k < DK; k += 2) {
        int i0 = ((tid << 4) + (((k)     >> 2) ^ (tid & 15))) * 4 + ((k)     & 3);
        int i1 = ((tid << 4) + (((k + 1) >> 2) ^ (tid & 15))) * 4 + ((k + 1) & 3);
        float e0 = __expf(stf[i0]);
        float e1 = __expf(stf[i1]);
        stf[i0] = e0; stf[i1] = e1;
        s0 += e0; s1 += e1;
    }
    float inv = 1.0f / (s0 + s1);
    #pragma unroll 8
    for (int k = 0; k < DK; k++) {
        int i0 = ((tid << 4) + ((k >> 2) ^ (tid & 15))) * 4 + (k & 3);
        stf[i0] *= inv;
    }
    __syncthreads();

    // ---- coalesced store of probs ----
    float4* ogp = out4 + ((long)nrows + base) * 16;
    #pragma unroll
    for (int it = 0; it < 16; it++) {
        int idx = tid + it * BLOCK;
        if (idx < cnt4) {
            int r = idx >> 4, c = idx & 15;
            ogp[idx] = stage[(r << 4) + (c ^ (r & 15))];
        }
    }
}

extern "C" void kernel_launch(void* const* d_in, const int* in_sizes, int n_in,
                              void* d_out, int out_size) {
    const float4* feat4  = (const float4*)d_in[0];
    const float4* proto4 = (const float4*)d_in[1];
    float4* out4 = (float4*)d_out;
    int nrows = in_sizes[0] / DK;   // features is [N, 64]
    int grid = (nrows + BLOCK - 1) / BLOCK;
    assign_kernel<<<grid, BLOCK>>>(feat4, proto4, out4, nrows);
}

// round 2
// speedup vs baseline: 1.6660x; 1.6660x over previous
#include <cuda_runtime.h>

#define DK 64
#define RPB 64          // rows per block
#define THREADS 128

using ull = unsigned long long;

__device__ __forceinline__ ull fma2(ull a, ull b, ull c) {
    ull d;
    asm("fma.rn.f32x2 %0, %1, %2, %3;" : "=l"(d) : "l"(a), "l"(b), "l"(c));
    return d;
}
__device__ __forceinline__ float2 unpack2(ull v) {
    float2 r;
    asm("mov.b64 {%0, %1}, %2;" : "=f"(r.x), "=f"(r.y) : "l"(v));
    return r;
}

// Register-blocked GEMM: each thread owns a 4-row x 8-proto output tile.
// Warp layout: lane = rg*8 + pg  (rg: 4 row-groups of 4 rows, pg: 8 proto-groups of 8).
// SMEM tiles are XOR-swizzled by the lane-varying group index so every LDS.128
// hits distinct bank quads (features: ^rg, protos: ^pg).
__global__ __launch_bounds__(THREADS) void assign_kernel(
    const float4* __restrict__ feat4,
    const float4* __restrict__ proto4,
    float* __restrict__ out,
    int nrows)
{
    __shared__ float4 feat_s[RPB * 16];    // 16 KB, col ^ ((row>>2)&3)
    __shared__ float4 proto_s[DK * 16];    // 16 KB, col ^ ((k>>3)&7)
    __shared__ float scale_s[RPB];

    const int tid = threadIdx.x;
    const long base = (long)blockIdx.x * RPB;
    const int rows = min(RPB, nrows - (int)base);
    const int cnt4 = rows * 16;

    // ---- stage prototypes (swizzled by pg = (k>>3)&7) ----
    #pragma unroll
    for (int i = 0; i < 8; i++) {
        int idx = tid + i * THREADS;           // 0..1023
        int k = idx >> 4, c = idx & 15;
        proto_s[(k << 4) + (c ^ ((k >> 3) & 7))] = proto4[idx];
    }

    // ---- stage features (swizzled by rg = (row>>2)&3), zero-fill OOB ----
    const float4* g = feat4 + base * 16;
    #pragma unroll
    for (int i = 0; i < 8; i++) {
        int idx = tid + i * THREADS;
        float4 v = make_float4(0.f, 0.f, 0.f, 0.f);
        if (idx < cnt4) v = g[idx];
        int r = idx >> 4, c = idx & 15;
        feat_s[(r << 4) + (c ^ ((r >> 2) & 3))] = v;
    }
    __syncthreads();

    // ---- row scales: 2 threads per row; scale = 1/(max(||f||,eps)*tau) ----
    {
        int row = tid >> 1, half = tid & 1;
        int sw = (row >> 2) & 3;
        float s = 0.f;
        #pragma unroll
        for (int i = 0; i < 8; i++) {
            int d4 = half * 8 + i;
            float4 v = feat_s[(row << 4) + (d4 ^ sw)];
            s += v.x * v.x + v.y * v.y + v.z * v.z + v.w * v.w;
        }
        s += __shfl_xor_sync(0xffffffffu, s, 1);
        if (half == 0)
            scale_s[row] = 1.0f / (fmaxf(sqrtf(s), 1e-8f) * 0.2f);
    }
    __syncthreads();

    const int w = tid >> 5, lane = tid & 31;
    const int rg = lane >> 3, pg = lane & 7;
    const int row_base = w * 16 + rg * 4;

    ull acc[4][8];
    #pragma unroll
    for (int i = 0; i < 4; i++)
        #pragma unroll
        for (int j = 0; j < 8; j++)
            acc[i][j] = 0ull;

    const ulonglong2* fs = (const ulonglong2*)feat_s;   // 16B units == float4 index
    const ulonglong2* ps = (const ulonglong2*)proto_s;

    // ---- main GEMM: 16 d4-steps x 64 FFMA2 each ----
    #pragma unroll
    for (int d4 = 0; d4 < 16; d4++) {
        ulonglong2 fr[4];
        #pragma unroll
        for (int i = 0; i < 4; i++)
            fr[i] = fs[((row_base + i) << 4) + (d4 ^ rg)];
        #pragma unroll
        for (int j = 0; j < 8; j++) {
            ulonglong2 p = ps[(((pg << 3) + j) << 4) + (d4 ^ pg)];
            #pragma unroll
            for (int i = 0; i < 4; i++) {
                acc[i][j] = fma2(fr[i].x, p.x, acc[i][j]);
                acc[i][j] = fma2(fr[i].y, p.y, acc[i][j]);
            }
        }
    }

    // ---- epilogue: scale, exp, 8-lane row-sum reduce, direct coalesced STG ----
    #pragma unroll
    for (int i = 0; i < 4; i++) {
        int row = row_base + i;
        float sc = scale_s[row];             // zero-filled rows -> lg=0, safe
        float lg[8], ex[8];
        float s = 0.f;
        #pragma unroll
        for (int j = 0; j < 8; j++) {
            float2 v = unpack2(acc[i][j]);
            lg[j] = (v.x + v.y) * sc;
            ex[j] = __expf(lg[j]);           // |lg| <= 5: no max-shift needed
            s += ex[j];
        }
        s += __shfl_xor_sync(0xffffffffu, s, 1);
        s += __shfl_xor_sync(0xffffffffu, s, 2);
        s += __shfl_xor_sync(0xffffffffu, s, 4);
        float inv = 1.0f / s;

        if (row < rows) {
            float4* lo = (float4*)(out + (base + row) * 64 + pg * 8);
            lo[0] = make_float4(lg[0], lg[1], lg[2], lg[3]);
            lo[1] = make_float4(lg[4], lg[5], lg[6], lg[7]);
            float4* po = (float4*)(out + ((long)nrows + base + row) * 64 + pg * 8);
            po[0] = make_float4(ex[0] * inv, ex[1] * inv, ex[2] * inv, ex[3] * inv);
            po[1] = make_float4(ex[4] * inv, ex[5] * inv, ex[6] * inv, ex[7] * inv);
        }
    }
}

extern "C" void kernel_launch(void* const* d_in, const int* in_sizes, int n_in,
                              void* d_out, int out_size) {
    const float4* feat4  = (const float4*)d_in[0];
    const float4* proto4 = (const float4*)d_in[1];
    float* out = (float*)d_out;
    int nrows = in_sizes[0] / DK;
    int grid = (nrows + RPB - 1) / RPB;
    assign_kernel<<<grid, THREADS>>>(feat4, proto4, out, nrows);
}

// round 4
// speedup vs baseline: 2.9763x; 1.7865x over previous
#include <cuda_runtime.h>
#include <cstdint>

#define RPB 128
#define THREADS 128

static __device__ __forceinline__ uint32_t cvt_tf32(float f) {
    uint32_t r;
    asm("cvt.rn.tf32.f32 %0, %1;" : "=r"(r) : "f"(f));
    return r;
}

static __device__ __forceinline__ void mma_tf32(float* d,
    uint32_t a0, uint32_t a1, uint32_t a2, uint32_t a3,
    uint32_t b0, uint32_t b1)
{
    asm volatile("mma.sync.aligned.m16n8k8.row.col.f32.tf32.tf32.f32 "
        "{%0,%1,%2,%3}, {%4,%5,%6,%7}, {%8,%9}, {%0,%1,%2,%3};"
        : "+f"(d[0]), "+f"(d[1]), "+f"(d[2]), "+f"(d[3])
        : "r"(a0), "r"(a1), "r"(a2), "r"(a3), "r"(b0), "r"(b1));
}

// Per CTA: 128 feature rows x 64 protos via mma.sync tf32.
// SMEM tiles row-major, 64 tf32/row; float-k swizzled by k ^ (4*(row&7)) so
// fragment gathers (lanes: gid 0..7 = rows/cols, tig 0..3 = k) are bank-conflict-free.
__global__ __launch_bounds__(THREADS, 4) void assign_mma_kernel(
    const float4* __restrict__ feat4,
    const float4* __restrict__ proto4,
    float* __restrict__ out, int nrows)
{
    __shared__ uint4 A_s[RPB * 16];   // 32 KB
    __shared__ uint4 B_s[64 * 16];    // 16 KB

    const int tid = threadIdx.x;
    const long base = (long)blockIdx.x * RPB;
    const int rows = min(RPB, nrows - (int)base);
    const int cnt4 = rows * 16;

    // ---- stage features (tf32, swizzled); zero-fill OOB rows ----
    const float4* g = feat4 + base * 16;
    #pragma unroll
    for (int i = 0; i < 16; i++) {
        int idx = tid + i * THREADS;
        float4 v = make_float4(0.f, 0.f, 0.f, 0.f);
        if (idx < cnt4) v = g[idx];
        uint4 t;
        t.x = cvt_tf32(v.x); t.y = cvt_tf32(v.y);
        t.z = cvt_tf32(v.z); t.w = cvt_tf32(v.w);
        int r = idx >> 4, c = idx & 15;
        A_s[(r << 4) | (c ^ (r & 7))] = t;
    }
    // ---- stage prototypes ----
    #pragma unroll
    for (int i = 0; i < 8; i++) {
        int idx = tid + i * THREADS;
        float4 v = proto4[idx];
        uint4 t;
        t.x = cvt_tf32(v.x); t.y = cvt_tf32(v.y);
        t.z = cvt_tf32(v.z); t.w = cvt_tf32(v.w);
        int n = idx >> 4, c = idx & 15;
        B_s[(n << 4) | (c ^ (n & 7))] = t;
    }
    __syncthreads();

    const int w = tid >> 5, lane = tid & 31;
    const int gid = lane >> 2, tig = lane & 3;
    const int sw = gid << 2;
    const int rb = w * 32;

    const uint32_t* As32 = (const uint32_t*)A_s;
    const uint32_t* Bs32 = (const uint32_t*)B_s;
    const float4* Af4 = (const float4*)A_s;

    // ---- per-row scales: sc = 5 / max(||f||, eps)   (tau = 0.2) ----
    float sc[2][2];
    #pragma unroll
    for (int ch = 0; ch < 2; ch++) {
        int r0 = rb + ch * 16 + gid;
        float s0 = 0.f, s1 = 0.f;
        #pragma unroll
        for (int q = 0; q < 4; q++) {
            int c = (tig * 4 + q) ^ gid;           // row&7 == gid for both halves
            float4 v0 = Af4[(r0 << 4) | c];
            float4 v1 = Af4[((r0 + 8) << 4) | c];
            s0 += v0.x * v0.x + v0.y * v0.y + v0.z * v0.z + v0.w * v0.w;
            s1 += v1.x * v1.x + v1.y * v1.y + v1.z * v1.z + v1.w * v1.w;
        }
        s0 += __shfl_xor_sync(~0u, s0, 1); s0 += __shfl_xor_sync(~0u, s0, 2);
        s1 += __shfl_xor_sync(~0u, s1, 1); s1 += __shfl_xor_sync(~0u, s1, 2);
        sc[ch][0] = 5.0f / fmaxf(sqrtf(s0), 1e-8f);
        sc[ch][1] = 5.0f / fmaxf(sqrtf(s1), 1e-8f);
    }

    // ---- GEMM: 8 k-steps x (8 B-frags reused across 2 m-chunks x 8 mma) ----
    float acc[2][8][4];
    #pragma unroll
    for (int ch = 0; ch < 2; ch++)
        #pragma unroll
        for (int j = 0; j < 8; j++)
            #pragma unroll
            for (int e = 0; e < 4; e++) acc[ch][j][e] = 0.f;

    #pragma unroll
    for (int ks = 0; ks < 8; ks++) {
        int o0 = (ks * 8 + tig) ^ sw;
        int o1 = (ks * 8 + tig + 4) ^ sw;
        uint32_t b0[8], b1[8];
        #pragma unroll
        for (int j = 0; j < 8; j++) {
            int n = j * 8 + gid;
            b0[j] = Bs32[n * 64 + o0];
            b1[j] = Bs32[n * 64 + o1];
        }
        #pragma unroll
        for (int ch = 0; ch < 2; ch++) {
            int r = rb + ch * 16 + gid;
            uint32_t a0 = As32[r * 64 + o0];
            uint32_t a1 = As32[(r + 8) * 64 + o0];
            uint32_t a2 = As32[r * 64 + o1];
            uint32_t a3 = As32[(r + 8) * 64 + o1];
            #pragma unroll
            for (int j = 0; j < 8; j++)
                mma_tf32(acc[ch][j], a0, a1, a2, a3, b0[j], b1[j]);
        }
    }

    // ---- epilogue: scale, store logits, exp, quad-reduce, store probs ----
    #pragma unroll
    for (int ch = 0; ch < 2; ch++) {
        #pragma unroll
        for (int hf = 0; hf < 2; hf++) {
            int r = rb + ch * 16 + hf * 8 + gid;
            float scv = sc[ch][hf];
            bool ok = (r < rows);
            long orow = base + r;
            float* lo = out + orow * 64 + 2 * tig;
            float ex[16];
            float s = 0.f;
            #pragma unroll
            for (int j = 0; j < 8; j++) {
                float l0 = acc[ch][j][2 * hf]     * scv;
                float l1 = acc[ch][j][2 * hf + 1] * scv;
                if (ok) *(float2*)(lo + j * 8) = make_float2(l0, l1);
                float e0 = __expf(l0), e1 = __expf(l1);   // |logit| <= 5
                ex[2 * j] = e0; ex[2 * j + 1] = e1;
                s += e0 + e1;
            }
            s += __shfl_xor_sync(~0u, s, 1);
            s += __shfl_xor_sync(~0u, s, 2);
            float inv = 1.0f / s;
            float* po = out + ((long)nrows + orow) * 64 + 2 * tig;
            #pragma unroll
            for (int j = 0; j < 8; j++)
                if (ok) *(float2*)(po + j * 8) =
                    make_float2(ex[2 * j] * inv, ex[2 * j + 1] * inv);
        }
    }
}

extern "C" void kernel_launch(void* const* d_in, const int* in_sizes, int n_in,
                              void* d_out, int out_size) {
    const float4* feat4  = (const float4*)d_in[0];
    const float4* proto4 = (const float4*)d_in[1];
    float* out = (float*)d_out;
    int nrows = in_sizes[0] / 64;
    int grid = (nrows + RPB - 1) / RPB;
    assign_mma_kernel<<<grid, THREADS>>>(feat4, proto4, out, nrows);
}

// round 5
// speedup vs baseline: 3.0859x; 1.0368x over previous
#include <cuda_runtime.h>
#include <cstdint>

#define RPB 128
#define THREADS 128

static __device__ __forceinline__ uint32_t cvt_tf32(float f) {
    uint32_t r;
    asm("cvt.rn.tf32.f32 %0, %1;" : "=r"(r) : "f"(f));
    return r;
}

static __device__ __forceinline__ void mma_tf32(float* d,
    uint32_t a0, uint32_t a1, uint32_t a2, uint32_t a3,
    uint32_t b0, uint32_t b1)
{
    asm volatile("mma.sync.aligned.m16n8k8.row.col.f32.tf32.tf32.f32 "
        "{%0,%1,%2,%3}, {%4,%5,%6,%7}, {%8,%9}, {%0,%1,%2,%3};"
        : "+f"(d[0]), "+f"(d[1]), "+f"(d[2]), "+f"(d[3])
        : "r"(a0), "r"(a1), "r"(a2), "r"(a3), "r"(b0), "r"(b1));
}

// Quad shuffle-transpose: lanes tig/tig^1 exchange 2-float slivers so each
// lane stores a full float4 (64B contiguous per quad per row).
static __device__ __forceinline__ void quad_store_row(
    const float (&v)[8][2], float* rowp, int odd, int tigh, bool ok)
{
    #pragma unroll
    for (int m = 0; m < 4; m++) {
        const int j0 = 2 * m, j1 = 2 * m + 1;
        float send0 = odd ? v[j0][0] : v[j1][0];
        float send1 = odd ? v[j0][1] : v[j1][1];
        float own0  = odd ? v[j1][0] : v[j0][0];
        float own1  = odd ? v[j1][1] : v[j0][1];
        float r0 = __shfl_xor_sync(~0u, send0, 1);
        float r1 = __shfl_xor_sync(~0u, send1, 1);
        float4 c;
        c.x = odd ? r0 : own0;
        c.y = odd ? r1 : own1;
        c.z = odd ? own0 : r0;
        c.w = odd ? own1 : r1;
        int colbase = 16 * m + 4 * tigh + 8 * odd;
        if (ok) *(float4*)(rowp + colbase) = c;
    }
}

__global__ __launch_bounds__(THREADS, 4) void assign_mma_kernel(
    const float4* __restrict__ feat4,
    const float4* __restrict__ proto4,
    float* __restrict__ out, int nrows)
{
    __shared__ uint4 A_s[RPB * 16];   // 32 KB
    __shared__ uint4 B_s[64 * 16];    // 16 KB

    const int tid = threadIdx.x;
    const long base = (long)blockIdx.x * RPB;
    const int rows = min(RPB, nrows - (int)base);
    const int cnt4 = rows * 16;

    // ---- stage features (tf32, swizzled); zero-fill OOB rows ----
    const float4* g = feat4 + base * 16;
    #pragma unroll
    for (int i = 0; i < 16; i++) {
        int idx = tid + i * THREADS;
        float4 v = make_float4(0.f, 0.f, 0.f, 0.f);
        if (idx < cnt4) v = g[idx];
        uint4 t;
        t.x = cvt_tf32(v.x); t.y = cvt_tf32(v.y);
        t.z = cvt_tf32(v.z); t.w = cvt_tf32(v.w);
        int r = idx >> 4, c = idx & 15;
        A_s[(r << 4) | (c ^ (r & 7))] = t;
    }
    // ---- stage prototypes ----
    #pragma unroll
    for (int i = 0; i < 8; i++) {
        int idx = tid + i * THREADS;
        float4 v = proto4[idx];
        uint4 t;
        t.x = cvt_tf32(v.x); t.y = cvt_tf32(v.y);
        t.z = cvt_tf32(v.z); t.w = cvt_tf32(v.w);
        int n = idx >> 4, c = idx & 15;
        B_s[(n << 4) | (c ^ (n & 7))] = t;
    }
    __syncthreads();

    const int w = tid >> 5, lane = tid & 31;
    const int gid = lane >> 2, tig = lane & 3;
    const int odd = tig & 1, tigh = tig >> 1;
    const int sw = gid << 2;
    const int rb = w * 32;

    const uint32_t* As32 = (const uint32_t*)A_s;
    const uint32_t* Bs32 = (const uint32_t*)B_s;
    const float4* Af4 = (const float4*)A_s;

    // ---- per-row scales: sc = 5 / max(||f||, eps)   (tau = 0.2) ----
    float sc[2][2];
    #pragma unroll
    for (int ch = 0; ch < 2; ch++) {
        int r0 = rb + ch * 16 + gid;
        float s0 = 0.f, s1 = 0.f;
        #pragma unroll
        for (int q = 0; q < 4; q++) {
            int c = (tig * 4 + q) ^ gid;           // row&7 == gid for both halves
            float4 v0 = Af4[(r0 << 4) | c];
            float4 v1 = Af4[((r0 + 8) << 4) | c];
            s0 += v0.x * v0.x + v0.y * v0.y + v0.z * v0.z + v0.w * v0.w;
            s1 += v1.x * v1.x + v1.y * v1.y + v1.z * v1.z + v1.w * v1.w;
        }
        s0 += __shfl_xor_sync(~0u, s0, 1); s0 += __shfl_xor_sync(~0u, s0, 2);
        s1 += __shfl_xor_sync(~0u, s1, 1); s1 += __shfl_xor_sync(~0u, s1, 2);
        sc[ch][0] = 5.0f / fmaxf(sqrtf(s0), 1e-8f);
        sc[ch][1] = 5.0f / fmaxf(sqrtf(s1), 1e-8f);
    }

    // ---- GEMM: 8 k-steps x (8 B-frags reused across 2 m-chunks x 8 mma) ----
    float acc[2][8][4];
    #pragma unroll
    for (int ch = 0; ch < 2; ch++)
        #pragma unroll
        for (int j = 0; j < 8; j++)
            #pragma unroll
            for (int e = 0; e < 4; e++) acc[ch][j][e] = 0.f;

    #pragma unroll
    for (int ks = 0; ks < 8; ks++) {
        int o0 = (ks * 8 + tig) ^ sw;
        int o1 = (ks * 8 + tig + 4) ^ sw;
        uint32_t b0[8], b1[8];
        #pragma unroll
        for (int j = 0; j < 8; j++) {
            int n = j * 8 + gid;
            b0[j] = Bs32[n * 64 + o0];
            b1[j] = Bs32[n * 64 + o1];
        }
        #pragma unroll
        for (int ch = 0; ch < 2; ch++) {
            int r = rb + ch * 16 + gid;
            uint32_t a0 = As32[r * 64 + o0];
            uint32_t a1 = As32[(r + 8) * 64 + o0];
            uint32_t a2 = As32[r * 64 + o1];
            uint32_t a3 = As32[(r + 8) * 64 + o1];
            #pragma unroll
            for (int j = 0; j < 8; j++)
                mma_tf32(acc[ch][j], a0, a1, a2, a3, b0[j], b1[j]);
        }
    }

    // ---- epilogue: scale, exp, quad-reduce; shuffle-transposed 16B stores ----
    #pragma unroll
    for (int ch = 0; ch < 2; ch++) {
        #pragma unroll
        for (int hf = 0; hf < 2; hf++) {
            int r = rb + ch * 16 + hf * 8 + gid;
            float scv = sc[ch][hf];
            bool ok = (r < rows);
            long orow = base + r;

            float lg[8][2], ex[8][2];
            float s = 0.f;
            #pragma unroll
            for (int j = 0; j < 8; j++) {
                lg[j][0] = acc[ch][j][2 * hf]     * scv;
                lg[j][1] = acc[ch][j][2 * hf + 1] * scv;
                ex[j][0] = __expf(lg[j][0]);       // |logit| <= 5
                ex[j][1] = __expf(lg[j][1]);
                s += ex[j][0] + ex[j][1];
            }
            s += __shfl_xor_sync(~0u, s, 1);
            s += __shfl_xor_sync(~0u, s, 2);
            float inv = 1.0f / s;
            #pragma unroll
            for (int j = 0; j < 8; j++) {
                ex[j][0] *= inv;
                ex[j][1] *= inv;
            }

            quad_store_row(lg, out + orow * 64, odd, tigh, ok);
            quad_store_row(ex, out + ((long)nrows + orow) * 64, odd, tigh, ok);
        }
    }
}

extern "C" void kernel_launch(void* const* d_in, const int* in_sizes, int n_in,
                              void* d_out, int out_size) {
    const float4* feat4  = (const float4*)d_in[0];
    const float4* proto4 = (const float4*)d_in[1];
    float* out = (float*)d_out;
    int nrows = in_sizes[0] / 64;
    int grid = (nrows + RPB - 1) / RPB;
    assign_mma_kernel<<<grid, THREADS>>>(feat4, proto4, out, nrows);
}